// round 16
// baseline (speedup 1.0000x reference)
#include <cuda_runtime.h>
#include <cuda_fp16.h>

// Capsule routing, B=32, I=1024, O=64, D_in=16, D_out=32.
// R15: uhat covers 16 i's per block (s0 partials at 64-granularity -> half
//      the partial write + half the v0-reduce read); k_rsq templated on
//      partial count with 4-way reduce tree. route = proven form, untouched.

#define B_   32
#define I_   1024
#define O_   64
#define DN   16
#define DD   32
#define OD   2048      // O_*DD
#define CHU  16        // capsules (i) per uhat block
#define CH   8         // capsules (i) per route chunk
#define NCH  128       // route partial granularity
#define NCU  64        // uhat s0 partial granularity
#define SPAD 40        // slab row stride (halfs)

__device__ __half  g_uhat [(size_t)B_ * I_ * OD];  // 134 MB (fp16)
__device__ __half  g_parth[(size_t)NCH * B_ * OD]; // 16.8 MB fp16 partials
__device__ __half2 g_bij16[(size_t)B_ * I_ * 32];  // 4 MB fp16 logits (o, o+32)
__device__ float   g_v    [(size_t)B_ * OD];       // v_j

__device__ __forceinline__ unsigned h2u(const __half2 h) {
    return *reinterpret_cast<const unsigned*>(&h);
}

// ---------------------------------------------------------------------------
// K1: u_hat (fp16) + s0 chunk partials, via tensor cores.
// grid = (8 od-slices, 64 chunks-of-16), 256 threads. Warp w covers 32 od.
// B-frags straight from global W (LDG.64 + cvt); C staged through per-warp
// SMEM slab -> full-sector STG.128; f32 accumulators fuse the s0 partial
// over all 16 i's.
// ---------------------------------------------------------------------------
__global__ __launch_bounds__(256, 3) void k_uhat(const float* __restrict__ x,
                                                 const float* __restrict__ W) {
    __shared__ __half xsm[CHU][B_][DN];       // 16 KB
    __shared__ __half slab[8][B_][SPAD];      // 20 KB

    const int t  = threadIdx.x;
    const int w  = t >> 5;
    const int l  = t & 31;
    const int i0  = blockIdx.y * CHU;
    const int odw = blockIdx.x * 256 + w * 32;

    // x[:, i0:i0+16, :] -> fp16 SMEM. 2048 float4, 8 per thread.
#pragma unroll
    for (int k = 0; k < 8; k++) {
        const int idx = t + k * 256;
        const int b  = idx >> 6;
        const int r  = idx & 63;
        const int il = r >> 2;
        const int kq = r & 3;
        const float4 f = *reinterpret_cast<const float4*>(
            x + (size_t)b * (I_ * DN) + (i0 + il) * DN + kq * 4);
        uint2 st;
        st.x = h2u(__floats2half2_rn(f.x, f.y));
        st.y = h2u(__floats2half2_rn(f.z, f.w));
        *reinterpret_cast<uint2*>(&xsm[il][b][kq * 4]) = st;
    }
    __syncthreads();

    const int lq = l >> 2;
    const int lr = (l & 3) * 2;

    float acc[8][4];
#pragma unroll
    for (int j = 0; j < 8; j++)
#pragma unroll
        for (int c = 0; c < 4; c++) acc[j][c] = 0.f;

#pragma unroll 1
    for (int il = 0; il < CHU; il++) {
        const int i = i0 + il;

        unsigned a[2][4];
#pragma unroll
        for (int mt = 0; mt < 2; mt++) {
            const int bb = mt * 16 + lq;
            a[mt][0] = *reinterpret_cast<const unsigned*>(&xsm[il][bb][lr]);
            a[mt][1] = *reinterpret_cast<const unsigned*>(&xsm[il][bb + 8][lr]);
            a[mt][2] = *reinterpret_cast<const unsigned*>(&xsm[il][bb][lr + 8]);
            a[mt][3] = *reinterpret_cast<const unsigned*>(&xsm[il][bb + 8][lr + 8]);
        }

        const float* wbase = W + ((size_t)i * OD + odw) * DN;
#pragma unroll
        for (int nt = 0; nt < 4; nt++) {
            const float* wrow = wbase + (nt * 8 + lq) * DN;
            const float2 f2a = *reinterpret_cast<const float2*>(wrow + lr);
            const float2 f2b = *reinterpret_cast<const float2*>(wrow + lr + 8);
            const unsigned bf0 = h2u(__floats2half2_rn(f2a.x, f2a.y));
            const unsigned bf1 = h2u(__floats2half2_rn(f2b.x, f2b.y));
            const int odl = nt * 8 + lr;
#pragma unroll
            for (int mt = 0; mt < 2; mt++) {
                float c0 = 0.f, c1 = 0.f, c2 = 0.f, c3 = 0.f;
                asm volatile(
                    "mma.sync.aligned.m16n8k16.row.col.f32.f16.f16.f32 "
                    "{%0,%1,%2,%3}, {%4,%5,%6,%7}, {%8,%9}, {%0,%1,%2,%3};"
                    : "+f"(c0), "+f"(c1), "+f"(c2), "+f"(c3)
                    : "r"(a[mt][0]), "r"(a[mt][1]), "r"(a[mt][2]), "r"(a[mt][3]),
                      "r"(bf0), "r"(bf1));
                acc[nt * 2 + mt][0] += c0;
                acc[nt * 2 + mt][1] += c1;
                acc[nt * 2 + mt][2] += c2;
                acc[nt * 2 + mt][3] += c3;
                const int b0 = mt * 16 + lq;
                *reinterpret_cast<unsigned*>(&slab[w][b0][odl]) =
                    h2u(__floats2half2_rn(c0, c1));
                *reinterpret_cast<unsigned*>(&slab[w][b0 + 8][odl]) =
                    h2u(__floats2half2_rn(c2, c3));
            }
        }
        __syncwarp();
#pragma unroll
        for (int p = 0; p < 4; p++) {
            const int b = (l >> 2) + p * 8;
            const uint4 v =
                *reinterpret_cast<const uint4*>(&slab[w][b][(l & 3) * 8]);
            *reinterpret_cast<uint4*>(
                g_uhat + ((size_t)b * I_ + i) * OD + odw + (l & 3) * 8) = v;
        }
        __syncwarp();
    }

#pragma unroll
    for (int nt = 0; nt < 4; nt++) {
        const int odl = nt * 8 + lr;
#pragma unroll
        for (int mt = 0; mt < 2; mt++) {
            const int b0 = mt * 16 + lq;
            *reinterpret_cast<unsigned*>(&slab[w][b0][odl]) =
                h2u(__floats2half2_rn(acc[nt * 2 + mt][0], acc[nt * 2 + mt][1]));
            *reinterpret_cast<unsigned*>(&slab[w][b0 + 8][odl]) =
                h2u(__floats2half2_rn(acc[nt * 2 + mt][2], acc[nt * 2 + mt][3]));
        }
    }
    __syncwarp();
#pragma unroll
    for (int p = 0; p < 4; p++) {
        const int b = (l >> 2) + p * 8;
        const uint4 v =
            *reinterpret_cast<const uint4*>(&slab[w][b][(l & 3) * 8]);
        *reinterpret_cast<uint4*>(
            g_parth + ((size_t)blockIdx.y * B_ + b) * OD + odw + (l & 3) * 8) = v;
    }
}

// ---------------------------------------------------------------------------
// K2: reduce NP fp16 chunk partials + squash -> g_v or out.
// grid = (32 od-slices, 32 b), 256 threads; block covers 64 od.
// pg = 32 partial groups x (NP/32) loads each; 4-acc reduce tree.
// ---------------------------------------------------------------------------
template <int NP>
__global__ __launch_bounds__(256) void k_rsq(float factor,
                                             const float* __restrict__ bias,
                                             float* __restrict__ out) {
    __shared__ float red[32][64];    // 8 KB
    const int b  = blockIdx.y;
    const int t  = threadIdx.x;
    const int pg = t >> 3;           // 32 partial groups
    const int oc = t & 7;            // uint4 chunk within 64-od slice

    const uint4* gp = reinterpret_cast<const uint4*>(g_parth);
    const size_t base = (size_t)b * 256 + blockIdx.x * 8 + oc;

    float r[8] = {0, 0, 0, 0, 0, 0, 0, 0};
#pragma unroll
    for (int pp = 0; pp < NP; pp += 32) {
        const uint4 u = gp[(size_t)(pg + pp) * (B_ * 256) + base];
        const __half2* h = reinterpret_cast<const __half2*>(&u);
#pragma unroll
        for (int k = 0; k < 4; k++) {
            const float2 f = __half22float2(h[k]);
            r[k * 2 + 0] += f.x;
            r[k * 2 + 1] += f.y;
        }
    }
#pragma unroll
    for (int k = 0; k < 8; k++) red[pg][oc * 8 + k] = r[k];
    __syncthreads();

    if (t < 64) {
        float s0 = 0.f, s1 = 0.f, s2 = 0.f, s3 = 0.f;
#pragma unroll
        for (int g = 0; g < 32; g += 4) {
            s0 += red[g + 0][t];
            s1 += red[g + 1][t];
            s2 += red[g + 2][t];
            s3 += red[g + 3][t];
        }
        float s = ((s0 + s1) + (s2 + s3)) * factor;
        if (bias) s += bias[blockIdx.x * 64 + t];

        // warp = 32 consecutive od = exactly one o capsule
        float q = s * s;
#pragma unroll
        for (int sh = 16; sh > 0; sh >>= 1)
            q += __shfl_xor_sync(0xffffffffu, q, sh);
        const float scale = q / (1.f + q) * rsqrtf(q + 1e-8f);
        float* dst = out ? out : g_v;
        dst[(size_t)b * OD + blockIdx.x * 64 + t] = scale * s;
    }
}

// ---------------------------------------------------------------------------
// K3: one routing pass, register-resident, fp16 partial + fp16 b_ij.
// grid = (128, 32), 256 threads, minBlocks=3.
// ---------------------------------------------------------------------------
__global__ __launch_bounds__(256, 3) void k_route(int use_bij_in, int write_bij) {
    __shared__ float sa[CH][O_];
    __shared__ float sc[CH][O_];

    const int b  = blockIdx.y;
    const int i0 = blockIdx.x * CH;
    const int t  = threadIdx.x;
    const int o  = t >> 2;

    const uint4* usrc = reinterpret_cast<const uint4*>(
        g_uhat + ((size_t)b * I_ + i0) * OD) + t;
    uint4 u[CH];
#pragma unroll
    for (int il = 0; il < CH; il++) u[il] = usrc[il * 256];

    const float4* vsrc =
        reinterpret_cast<const float4*>(g_v + (size_t)b * OD) + t * 2;
    const float4 v0 = vsrc[0], v1 = vsrc[1];

#pragma unroll
    for (int il = 0; il < CH; il++) {
        const __half2* h = reinterpret_cast<const __half2*>(&u[il]);
        const float2 f0 = __half22float2(h[0]), f1 = __half22float2(h[1]);
        const float2 f2 = __half22float2(h[2]), f3 = __half22float2(h[3]);
        float a;
        a  = f0.x * v0.x;         a = fmaf(f0.y, v0.y, a);
        a  = fmaf(f1.x, v0.z, a); a = fmaf(f1.y, v0.w, a);
        a  = fmaf(f2.x, v1.x, a); a = fmaf(f2.y, v1.y, a);
        a  = fmaf(f3.x, v1.z, a); a = fmaf(f3.y, v1.w, a);
        a += __shfl_xor_sync(0xffffffffu, a, 1);
        a += __shfl_xor_sync(0xffffffffu, a, 2);
        if ((t & 3) == 0) sa[il][o] = a;
    }
    __syncthreads();

    {
        const int wid  = t >> 5;
        const int lane = t & 31;
        const int i = i0 + wid;
        float a0 = sa[wid][lane];
        float a1 = sa[wid][lane + 32];
        if (use_bij_in) {
            const float2 f =
                __half22float2(g_bij16[((size_t)b * I_ + i) * 32 + lane]);
            a0 += f.x;
            a1 += f.y;
        }
        if (write_bij) {
            g_bij16[((size_t)b * I_ + i) * 32 + lane] =
                __floats2half2_rn(a0, a1);
        }
        float m = fmaxf(a0, a1);
#pragma unroll
        for (int s = 16; s > 0; s >>= 1)
            m = fmaxf(m, __shfl_xor_sync(0xffffffffu, m, s));
        const float e0 = __expf(a0 - m);
        const float e1 = __expf(a1 - m);
        float es = e0 + e1;
#pragma unroll
        for (int s = 16; s > 0; s >>= 1)
            es += __shfl_xor_sync(0xffffffffu, es, s);
        const float inv = 1.f / es;
        sc[wid][lane]      = e0 * inv;
        sc[wid][lane + 32] = e1 * inv;
    }
    __syncthreads();

    float4 r0 = {0,0,0,0}, r1 = {0,0,0,0};
#pragma unroll
    for (int il = 0; il < CH; il++) {
        const float s = sc[il][o];
        const __half2* h = reinterpret_cast<const __half2*>(&u[il]);
        const float2 f0 = __half22float2(h[0]), f1 = __half22float2(h[1]);
        const float2 f2 = __half22float2(h[2]), f3 = __half22float2(h[3]);
        r0.x = fmaf(s, f0.x, r0.x); r0.y = fmaf(s, f0.y, r0.y);
        r0.z = fmaf(s, f1.x, r0.z); r0.w = fmaf(s, f1.y, r0.w);
        r1.x = fmaf(s, f2.x, r1.x); r1.y = fmaf(s, f2.y, r1.y);
        r1.z = fmaf(s, f3.x, r1.z); r1.w = fmaf(s, f3.y, r1.w);
    }
    uint4 st;
    st.x = h2u(__floats2half2_rn(r0.x, r0.y));
    st.y = h2u(__floats2half2_rn(r0.z, r0.w));
    st.z = h2u(__floats2half2_rn(r1.x, r1.y));
    st.w = h2u(__floats2half2_rn(r1.z, r1.w));
    reinterpret_cast<uint4*>(
        g_parth + ((size_t)blockIdx.x * B_ + b) * OD)[t] = st;
}

// ---------------------------------------------------------------------------
extern "C" void kernel_launch(void* const* d_in, const int* in_sizes, int n_in,
                              void* d_out, int out_size) {
    const float* x    = (const float*)d_in[0];   // [32,1024,16]
    const float* W    = (const float*)d_in[1];   // [1,1024,64,32,16]
    const float* bias = (const float*)d_in[2];   // [1,1,64,32]
    float* out = (float*)d_out;                  // [32,64,32]

    k_uhat<<<dim3(8, 64), 256>>>(x, W);                             // 1: u_hat + s0
    k_rsq<NCU><<<dim3(32, 32), 256>>>(1.f / 64.f, nullptr, nullptr);// 2: v0
    k_route<<<dim3(NCH, B_), 256>>>(0, 1);                          // 3
    k_rsq<NCH><<<dim3(32, 32), 256>>>(1.f, nullptr, nullptr);       // 4: v1
    k_route<<<dim3(NCH, B_), 256>>>(1, 0);                          // 5
    k_rsq<NCH><<<dim3(32, 32), 256>>>(1.f, bias, out);              // 6: out
}

// round 17
// speedup vs baseline: 1.0576x; 1.0576x over previous
#include <cuda_runtime.h>
#include <cuda_fp16.h>

// Capsule routing, B=32, I=1024, O=64, D_in=16, D_out=32.
// R16: exact R13 kernels (best bench 123.4us) + Programmatic Dependent
//      Launch: rsq triggers early; route loads u_hat (rsq-independent),
//      then grid-syncs before consuming v. Overlaps route's DRAM ramp
//      with rsq execution, twice.

#define B_   32
#define I_   1024
#define O_   64
#define DN   16
#define DD   32
#define OD   2048      // O_*DD
#define CH   8         // capsules (i) per chunk
#define NCH  128       // chunk count / partial granularity
#define SPAD 40        // slab row stride (halfs)

__device__ __half  g_uhat [(size_t)B_ * I_ * OD];  // 134 MB (fp16)
__device__ __half  g_parth[(size_t)NCH * B_ * OD]; // 16.8 MB fp16 partials
__device__ __half2 g_bij16[(size_t)B_ * I_ * 32];  // 4 MB fp16 logits (o, o+32)
__device__ float   g_v    [(size_t)B_ * OD];       // v_j

__device__ __forceinline__ unsigned h2u(const __half2 h) {
    return *reinterpret_cast<const unsigned*>(&h);
}

// ---------------------------------------------------------------------------
// K1: u_hat (fp16) + s0 chunk partials, via tensor cores.
// grid = (8 od-slices, 128 chunks), 256 threads. Warp w covers 32 od.
// (R13 form, unchanged — benched 123.4 total.)
// ---------------------------------------------------------------------------
__global__ __launch_bounds__(256, 3) void k_uhat(const float* __restrict__ x,
                                                 const float* __restrict__ W) {
    __shared__ __half xsm[CH][B_][DN];        // 8 KB
    __shared__ __half slab[8][B_][SPAD];      // 20 KB

    const int t  = threadIdx.x;
    const int w  = t >> 5;
    const int l  = t & 31;
    const int i0  = blockIdx.y * CH;
    const int odw = blockIdx.x * 256 + w * 32;

#pragma unroll
    for (int k = 0; k < 4; k++) {
        const int idx = t + k * 256;
        const int b  = idx >> 5;
        const int r  = idx & 31;
        const int il = r >> 2;
        const int kq = r & 3;
        const float4 f = *reinterpret_cast<const float4*>(
            x + (size_t)b * (I_ * DN) + (i0 + il) * DN + kq * 4);
        uint2 st;
        st.x = h2u(__floats2half2_rn(f.x, f.y));
        st.y = h2u(__floats2half2_rn(f.z, f.w));
        *reinterpret_cast<uint2*>(&xsm[il][b][kq * 4]) = st;
    }
    __syncthreads();

    const int lq = l >> 2;
    const int lr = (l & 3) * 2;

    float acc[8][4];
#pragma unroll
    for (int j = 0; j < 8; j++)
#pragma unroll
        for (int c = 0; c < 4; c++) acc[j][c] = 0.f;

#pragma unroll 1
    for (int il = 0; il < CH; il++) {
        const int i = i0 + il;

        unsigned a[2][4];
#pragma unroll
        for (int mt = 0; mt < 2; mt++) {
            const int bb = mt * 16 + lq;
            a[mt][0] = *reinterpret_cast<const unsigned*>(&xsm[il][bb][lr]);
            a[mt][1] = *reinterpret_cast<const unsigned*>(&xsm[il][bb + 8][lr]);
            a[mt][2] = *reinterpret_cast<const unsigned*>(&xsm[il][bb][lr + 8]);
            a[mt][3] = *reinterpret_cast<const unsigned*>(&xsm[il][bb + 8][lr + 8]);
        }

        const float* wbase = W + ((size_t)i * OD + odw) * DN;
#pragma unroll
        for (int nt = 0; nt < 4; nt++) {
            const float* wrow = wbase + (nt * 8 + lq) * DN;
            const float2 f2a = *reinterpret_cast<const float2*>(wrow + lr);
            const float2 f2b = *reinterpret_cast<const float2*>(wrow + lr + 8);
            const unsigned bf0 = h2u(__floats2half2_rn(f2a.x, f2a.y));
            const unsigned bf1 = h2u(__floats2half2_rn(f2b.x, f2b.y));
            const int odl = nt * 8 + lr;
#pragma unroll
            for (int mt = 0; mt < 2; mt++) {
                float c0 = 0.f, c1 = 0.f, c2 = 0.f, c3 = 0.f;
                asm volatile(
                    "mma.sync.aligned.m16n8k16.row.col.f32.f16.f16.f32 "
                    "{%0,%1,%2,%3}, {%4,%5,%6,%7}, {%8,%9}, {%0,%1,%2,%3};"
                    : "+f"(c0), "+f"(c1), "+f"(c2), "+f"(c3)
                    : "r"(a[mt][0]), "r"(a[mt][1]), "r"(a[mt][2]), "r"(a[mt][3]),
                      "r"(bf0), "r"(bf1));
                acc[nt * 2 + mt][0] += c0;
                acc[nt * 2 + mt][1] += c1;
                acc[nt * 2 + mt][2] += c2;
                acc[nt * 2 + mt][3] += c3;
                const int b0 = mt * 16 + lq;
                *reinterpret_cast<unsigned*>(&slab[w][b0][odl]) =
                    h2u(__floats2half2_rn(c0, c1));
                *reinterpret_cast<unsigned*>(&slab[w][b0 + 8][odl]) =
                    h2u(__floats2half2_rn(c2, c3));
            }
        }
        __syncwarp();
#pragma unroll
        for (int p = 0; p < 4; p++) {
            const int b = (l >> 2) + p * 8;
            const uint4 v =
                *reinterpret_cast<const uint4*>(&slab[w][b][(l & 3) * 8]);
            *reinterpret_cast<uint4*>(
                g_uhat + ((size_t)b * I_ + i) * OD + odw + (l & 3) * 8) = v;
        }
        __syncwarp();
    }

#pragma unroll
    for (int nt = 0; nt < 4; nt++) {
        const int odl = nt * 8 + lr;
#pragma unroll
        for (int mt = 0; mt < 2; mt++) {
            const int b0 = mt * 16 + lq;
            *reinterpret_cast<unsigned*>(&slab[w][b0][odl]) =
                h2u(__floats2half2_rn(acc[nt * 2 + mt][0], acc[nt * 2 + mt][1]));
            *reinterpret_cast<unsigned*>(&slab[w][b0 + 8][odl]) =
                h2u(__floats2half2_rn(acc[nt * 2 + mt][2], acc[nt * 2 + mt][3]));
        }
    }
    __syncwarp();
#pragma unroll
    for (int p = 0; p < 4; p++) {
        const int b = (l >> 2) + p * 8;
        const uint4 v =
            *reinterpret_cast<const uint4*>(&slab[w][b][(l & 3) * 8]);
        *reinterpret_cast<uint4*>(
            g_parth + ((size_t)blockIdx.y * B_ + b) * OD + odw + (l & 3) * 8) = v;
    }
}

// ---------------------------------------------------------------------------
// K2: reduce 128 fp16 chunk partials + squash -> g_v or out. (R13 form +
// early PDL trigger so the following route launches while we reduce.)
// grid = (32 od-slices, 32 b), 256 threads; block covers 64 od.
// ---------------------------------------------------------------------------
__global__ __launch_bounds__(256) void k_rsq(float factor,
                                             const float* __restrict__ bias,
                                             float* __restrict__ out) {
    cudaTriggerProgrammaticLaunchCompletion();

    __shared__ float red[32][64];    // 8 KB
    const int b  = blockIdx.y;
    const int t  = threadIdx.x;
    const int pg = t >> 3;           // 32 partial groups
    const int oc = t & 7;            // uint4 chunk within 64-od slice

    const uint4* gp = reinterpret_cast<const uint4*>(g_parth);
    const size_t base = (size_t)b * 256 + blockIdx.x * 8 + oc;

    const uint4 u0 = gp[(size_t)(pg +  0) * (B_ * 256) + base];
    const uint4 u1 = gp[(size_t)(pg + 32) * (B_ * 256) + base];
    const uint4 u2 = gp[(size_t)(pg + 64) * (B_ * 256) + base];
    const uint4 u3 = gp[(size_t)(pg + 96) * (B_ * 256) + base];

    float r[8];
    {
        const __half2* h0 = reinterpret_cast<const __half2*>(&u0);
        const __half2* h1 = reinterpret_cast<const __half2*>(&u1);
        const __half2* h2 = reinterpret_cast<const __half2*>(&u2);
        const __half2* h3 = reinterpret_cast<const __half2*>(&u3);
#pragma unroll
        for (int k = 0; k < 4; k++) {
            const float2 f0 = __half22float2(h0[k]);
            const float2 f1 = __half22float2(h1[k]);
            const float2 f2 = __half22float2(h2[k]);
            const float2 f3 = __half22float2(h3[k]);
            r[k * 2 + 0] = (f0.x + f1.x) + (f2.x + f3.x);
            r[k * 2 + 1] = (f0.y + f1.y) + (f2.y + f3.y);
        }
    }
#pragma unroll
    for (int k = 0; k < 8; k++) red[pg][oc * 8 + k] = r[k];
    __syncthreads();

    if (t < 64) {
        float s = 0.f;
#pragma unroll
        for (int g = 0; g < 32; g++) s += red[g][t];
        s *= factor;
        if (bias) s += bias[blockIdx.x * 64 + t];

        float q = s * s;
#pragma unroll
        for (int sh = 16; sh > 0; sh >>= 1)
            q += __shfl_xor_sync(0xffffffffu, q, sh);
        const float scale = q / (1.f + q) * rsqrtf(q + 1e-8f);
        float* dst = out ? out : g_v;
        dst[(size_t)b * OD + blockIdx.x * 64 + t] = scale * s;
    }
}

// ---------------------------------------------------------------------------
// K3: one routing pass, register-resident. (R13 form + grid-dependency sync:
// u_hat loads are issued BEFORE waiting on the preceding rsq; only v-dependent
// math and the g_parth/g_bij writes happen after.)
// grid = (128, 32), 256 threads, minBlocks=3.
// ---------------------------------------------------------------------------
__global__ __launch_bounds__(256, 3) void k_route(int use_bij_in, int write_bij) {
    __shared__ float sa[CH][O_];
    __shared__ float sc[CH][O_];

    const int b  = blockIdx.y;
    const int i0 = blockIdx.x * CH;
    const int t  = threadIdx.x;
    const int o  = t >> 2;

    // u_hat loads: independent of the preceding rsq (which writes only g_v)
    const uint4* usrc = reinterpret_cast<const uint4*>(
        g_uhat + ((size_t)b * I_ + i0) * OD) + t;
    uint4 u[CH];
#pragma unroll
    for (int il = 0; il < CH; il++) u[il] = usrc[il * 256];

    // wait for the preceding rsq grid (v producer) to complete
    cudaGridDependencySynchronize();

    const float4* vsrc =
        reinterpret_cast<const float4*>(g_v + (size_t)b * OD) + t * 2;
    const float4 v0 = vsrc[0], v1 = vsrc[1];

#pragma unroll
    for (int il = 0; il < CH; il++) {
        const __half2* h = reinterpret_cast<const __half2*>(&u[il]);
        const float2 f0 = __half22float2(h[0]), f1 = __half22float2(h[1]);
        const float2 f2 = __half22float2(h[2]), f3 = __half22float2(h[3]);
        float a;
        a  = f0.x * v0.x;         a = fmaf(f0.y, v0.y, a);
        a  = fmaf(f1.x, v0.z, a); a = fmaf(f1.y, v0.w, a);
        a  = fmaf(f2.x, v1.x, a); a = fmaf(f2.y, v1.y, a);
        a  = fmaf(f3.x, v1.z, a); a = fmaf(f3.y, v1.w, a);
        a += __shfl_xor_sync(0xffffffffu, a, 1);
        a += __shfl_xor_sync(0xffffffffu, a, 2);
        if ((t & 3) == 0) sa[il][o] = a;
    }
    __syncthreads();

    {
        const int wid  = t >> 5;
        const int lane = t & 31;
        const int i = i0 + wid;
        float a0 = sa[wid][lane];
        float a1 = sa[wid][lane + 32];
        if (use_bij_in) {
            const float2 f =
                __half22float2(g_bij16[((size_t)b * I_ + i) * 32 + lane]);
            a0 += f.x;
            a1 += f.y;
        }
        if (write_bij) {
            g_bij16[((size_t)b * I_ + i) * 32 + lane] =
                __floats2half2_rn(a0, a1);
        }
        float m = fmaxf(a0, a1);
#pragma unroll
        for (int s = 16; s > 0; s >>= 1)
            m = fmaxf(m, __shfl_xor_sync(0xffffffffu, m, s));
        const float e0 = __expf(a0 - m);
        const float e1 = __expf(a1 - m);
        float es = e0 + e1;
#pragma unroll
        for (int s = 16; s > 0; s >>= 1)
            es += __shfl_xor_sync(0xffffffffu, es, s);
        const float inv = 1.f / es;
        sc[wid][lane]      = e0 * inv;
        sc[wid][lane + 32] = e1 * inv;
    }
    __syncthreads();

    float4 r0 = {0,0,0,0}, r1 = {0,0,0,0};
#pragma unroll
    for (int il = 0; il < CH; il++) {
        const float s = sc[il][o];
        const __half2* h = reinterpret_cast<const __half2*>(&u[il]);
        const float2 f0 = __half22float2(h[0]), f1 = __half22float2(h[1]);
        const float2 f2 = __half22float2(h[2]), f3 = __half22float2(h[3]);
        r0.x = fmaf(s, f0.x, r0.x); r0.y = fmaf(s, f0.y, r0.y);
        r0.z = fmaf(s, f1.x, r0.z); r0.w = fmaf(s, f1.y, r0.w);
        r1.x = fmaf(s, f2.x, r1.x); r1.y = fmaf(s, f2.y, r1.y);
        r1.z = fmaf(s, f3.x, r1.z); r1.w = fmaf(s, f3.y, r1.w);
    }
    uint4 st;
    st.x = h2u(__floats2half2_rn(r0.x, r0.y));
    st.y = h2u(__floats2half2_rn(r0.z, r0.w));
    st.z = h2u(__floats2half2_rn(r1.x, r1.y));
    st.w = h2u(__floats2half2_rn(r1.z, r1.w));
    reinterpret_cast<uint4*>(
        g_parth + ((size_t)blockIdx.x * B_ + b) * OD)[t] = st;
}

// ---------------------------------------------------------------------------
extern "C" void kernel_launch(void* const* d_in, const int* in_sizes, int n_in,
                              void* d_out, int out_size) {
    const float* x    = (const float*)d_in[0];   // [32,1024,16]
    const float* W    = (const float*)d_in[1];   // [1,1024,64,32,16]
    const float* bias = (const float*)d_in[2];   // [1,1,64,32]
    float* out = (float*)d_out;                  // [32,64,32]

    k_uhat<<<dim3(8, 128), 256>>>(x, W);                        // 1: u_hat + s0
    k_rsq<<<dim3(32, 32), 256>>>(1.f / 64.f, nullptr, nullptr); // 2: v0

    // route launches with programmatic stream serialization (PDL)
    cudaLaunchAttribute attr[1];
    attr[0].id = cudaLaunchAttributeProgrammaticStreamSerialization;
    attr[0].val.programmaticStreamSerializationAllowed = 1;
    cudaLaunchConfig_t cfg = {};
    cfg.gridDim  = dim3(NCH, B_);
    cfg.blockDim = dim3(256);
    cfg.stream   = 0;
    cfg.attrs    = attr;
    cfg.numAttrs = 1;

    cudaLaunchKernelEx(&cfg, k_route, 0, 1);                    // 3
    k_rsq<<<dim3(32, 32), 256>>>(1.f, nullptr, nullptr);        // 4: v1
    cudaLaunchKernelEx(&cfg, k_route, 1, 0);                    // 5
    k_rsq<<<dim3(32, 32), 256>>>(1.f, bias, out);               // 6: out
}